// round 16
// baseline (speedup 1.0000x reference)
#include <cuda_runtime.h>
#include <cuda_bf16.h>
#include <cuda_fp16.h>
#include <math.h>
#include <stdint.h>

#define SEQ    2048
#define DIM    4096
#define NH     32
#define NKV    8
#define HD     128
#define KVDIM  (NKV*HD)

// ---------------------------------------------------------------------------
// Scratch (device globals)
// ---------------------------------------------------------------------------
static __device__ float g_qA[SEQ * DIM],   g_qB[SEQ * DIM];
static __device__ float g_kA[SEQ * KVDIM], g_kB[SEQ * KVDIM];
static __device__ float g_vA[SEQ * KVDIM], g_vB[SEQ * KVDIM];

static __device__ __half g_xh16[SEQ * DIM], g_xl16[SEQ * DIM];
static __device__ __half g_wq16[DIM * DIM];
static __device__ __half g_wk16[KVDIM * DIM];
static __device__ __half g_wv16[KVDIM * DIM];
static __device__ __half g_wo16[DIM * DIM];
static __device__ __half g_yh16[SEQ * DIM];

static __device__ __half g_q16[SEQ * DIM];
static __device__ __half g_k16[SEQ * KVDIM];
static __device__ __half g_vt16[KVDIM * SEQ];   // [kvh*128+d][s]

// ---------------------------------------------------------------------------
// Helpers
// ---------------------------------------------------------------------------
__device__ __forceinline__ uint32_t smem_u32(const void* p) {
    uint32_t a;
    asm("{ .reg .u64 t; cvta.to.shared.u64 t, %1; cvt.u32.u64 %0, t; }"
        : "=r"(a) : "l"(p));
    return a;
}

__device__ __forceinline__ void ldsm_x4(uint32_t* d, uint32_t addr) {
    asm volatile("ldmatrix.sync.aligned.m8n8.x4.shared.b16 {%0,%1,%2,%3}, [%4];"
                 : "=r"(d[0]), "=r"(d[1]), "=r"(d[2]), "=r"(d[3]) : "r"(addr));
}

__device__ __forceinline__ void mma16816h(float* c, const uint32_t* a,
                                          uint32_t b0, uint32_t b1) {
    asm volatile(
        "mma.sync.aligned.m16n8k16.row.col.f32.f16.f16.f32 "
        "{%0,%1,%2,%3}, {%4,%5,%6,%7}, {%8,%9}, {%0,%1,%2,%3};"
        : "+f"(c[0]), "+f"(c[1]), "+f"(c[2]), "+f"(c[3])
        : "r"(a[0]), "r"(a[1]), "r"(a[2]), "r"(a[3]), "r"(b0), "r"(b1));
}

#define CP_ASYNC16(dst, src) \
    asm volatile("cp.async.cg.shared.global [%0], [%1], 16;" :: "r"(dst), "l"(src))
#define CP_COMMIT() asm volatile("cp.async.commit_group;" ::: "memory")
#define CP_WAIT0()  asm volatile("cp.async.wait_group 0;"  ::: "memory")
#define CP_WAIT1()  asm volatile("cp.async.wait_group 1;"  ::: "memory")

// ---------------------------------------------------------------------------
// Pointwise kernels
// ---------------------------------------------------------------------------
__global__ void split16_kernel(const float* __restrict__ in,
                               __half* __restrict__ hi,
                               __half* __restrict__ lo, int n8)
{
    int i = blockIdx.x * blockDim.x + threadIdx.x;
    if (i >= n8) return;
#pragma unroll
    for (int half = 0; half < 2; half++) {
        float4 v = ((const float4*)in)[2 * i + half];
        float vv[4] = {v.x, v.y, v.z, v.w};
        __half h[4], l[4];
#pragma unroll
        for (int e = 0; e < 4; e++) {
            h[e] = __float2half_rn(vv[e]);
            l[e] = __float2half_rn(vv[e] - __half2float(h[e]));
        }
        __half2* hp = (__half2*)hi;
        __half2* lp = (__half2*)lo;
        hp[4 * i + 2 * half]     = __halves2half2(h[0], h[1]);
        hp[4 * i + 2 * half + 1] = __halves2half2(h[2], h[3]);
        lp[4 * i + 2 * half]     = __halves2half2(l[0], l[1]);
        lp[4 * i + 2 * half + 1] = __halves2half2(l[2], l[3]);
    }
}

__global__ void trunc16_kernel(const float* __restrict__ in,
                               __half* __restrict__ out, int n8)
{
    int i = blockIdx.x * blockDim.x + threadIdx.x;
    if (i >= n8) return;
#pragma unroll
    for (int half = 0; half < 2; half++) {
        float4 v = ((const float4*)in)[2 * i + half];
        __half2* op = (__half2*)out;
        op[4 * i + 2 * half]     = __floats2half2_rn(v.x, v.y);
        op[4 * i + 2 * half + 1] = __floats2half2_rn(v.z, v.w);
    }
}

// RoPE + scale on sum of two fp32 partials -> fp16
__global__ void rope_sum_f16_kernel(const float* __restrict__ xA,
                                    const float* __restrict__ xB,
                                    const float* __restrict__ fc,
                                    __half* __restrict__ o,
                                    int nheads, float scale, int total)
{
    int idx = blockIdx.x * blockDim.x + threadIdx.x;
    if (idx >= total) return;
    const int i = idx & 63;
    const int h = (idx >> 6) % nheads;
    const int s = idx / (64 * nheads);
    const float c  = fc[(s * 64 + i) * 2 + 0];
    const float sn = fc[(s * 64 + i) * 2 + 1];
    const size_t off = ((size_t)s * nheads + h) * HD + 2 * i;
    float2 va = *(const float2*)(xA + off);
    float2 vb = *(const float2*)(xB + off);
    const float vx = va.x + vb.x, vy = va.y + vb.y;
    float a = (vx * c - vy * sn) * scale;
    float b = (vy * c + vx * sn) * scale;
    *(__half2*)(o + off) = __floats2half2_rn(a, b);
}

// V transpose of partial sum -> fp16: [s][dl] -> [dl][s]
__global__ void vt_sum_f16_kernel(const float* __restrict__ vA,
                                  const float* __restrict__ vB,
                                  __half* __restrict__ vt)
{
    int idx = blockIdx.x * blockDim.x + threadIdx.x;
    const int s = idx & (SEQ - 1);
    const int dl = idx >> 11;
    if (dl >= KVDIM) return;
    const size_t off = (size_t)s * KVDIM + dl;
    vt[idx] = __float2half_rn(vA[off] + vB[off]);
}

// ---------------------------------------------------------------------------
// fp16 GEMM body over chunk range [c0, c1) with optional lo pass.
// CTA tile 128x256, 8 warps (2x4), K-chunk 64, 3-stage cp.async.
// Stage 64KB: A sub0 16K | A sub1 16K | B 32K.
// ---------------------------------------------------------------------------
#define F2_STAGE 65536
#define F2_SMEM  (3 * F2_STAGE + 1024)
#define F2_NC    (DIM / 64)

__device__ __forceinline__ void f2_stage_load(
    uint32_t st, const __half* __restrict__ Ah, const __half* __restrict__ Al,
    const __half* __restrict__ B, int row0, int col0, int k0, int tid)
{
    const int r  = tid >> 1;
    const int h  = tid & 1;
    const int sw = r & 7;
#pragma unroll
    for (int s = 0; s < 2; s++) {
        const __half* src = (h ? Al : Ah) + (size_t)(row0 + r) * DIM + k0 + s * 32;
        const uint32_t rowp = st + s * 16384 + r * 128;
#pragma unroll
        for (int u = 0; u < 4; u++)
            CP_ASYNC16(rowp + (((h * 4 + u) ^ sw) * 16), src + u * 8);
    }
#pragma unroll
    for (int p = 0; p < 2; p++) {
        const int rb = r + p * 128;
        const int swb = rb & 7;
        const __half* src = B + (size_t)(col0 + rb) * DIM + k0 + h * 32;
        const uint32_t rowp = st + 32768 + rb * 128;
#pragma unroll
        for (int u = 0; u < 4; u++)
            CP_ASYNC16(rowp + (((h * 4 + u) ^ swb) * 16), src + u * 8);
    }
}

__device__ __forceinline__ void gemm_f16_2p_body(
    const __half* __restrict__ Ah, const __half* __restrict__ Al,
    const __half* __restrict__ B, float* __restrict__ C, int Ntot,
    int row0, int col0, int c0, int c1, bool do_lo, char* smraw)
{
    const uint32_t sbase = (smem_u32(smraw) + 1023u) & ~1023u;
    const int tid = threadIdx.x;
    const int lid = tid & 31;
    const int wid = tid >> 5;
    const int wm  = wid & 1;
    const int wn  = wid >> 1;

    float acc[4][8][4];
#pragma unroll
    for (int i = 0; i < 4; i++)
#pragma unroll
        for (int j = 0; j < 8; j++)
#pragma unroll
            for (int q = 0; q < 4; q++) acc[i][j][q] = 0.f;

    f2_stage_load(sbase,            Ah, Al, B, row0, col0, c0 * 64,       tid);
    CP_COMMIT();
    f2_stage_load(sbase + F2_STAGE, Ah, Al, B, row0, col0, (c0 + 1) * 64, tid);
    CP_COMMIT();

    int cur = 0, nxt = 2;
    for (int c = c0; c < c1; c++) {
        CP_WAIT1();
        __syncthreads();
        if (c + 2 < c1) {
            f2_stage_load(sbase + nxt * F2_STAGE,
                          Ah, Al, B, row0, col0, (c + 2) * 64, tid);
            CP_COMMIT();
        }
        const uint32_t aBase = sbase + cur * F2_STAGE;
        const uint32_t bBase = aBase + 32768;
        cur = (cur == 2) ? 0 : cur + 1;
        nxt = (nxt == 2) ? 0 : nxt + 1;

#pragma unroll
        for (int ks = 0; ks < 4; ks++) {
            const int sub = ks >> 1;
            uint32_t ahf[4][4], alf[4][4], bf[4][4];
#pragma unroll
            for (int mt = 0; mt < 4; mt++) {
                const int r = wm * 64 + mt * 16 + (lid & 15);
                const int luh = (ks & 1) * 2 + (lid >> 4);
                const uint32_t rowp = aBase + sub * 16384 + r * 128;
                ldsm_x4(ahf[mt], rowp + ((luh ^ (r & 7)) * 16));
                if (do_lo)
                    ldsm_x4(alf[mt], rowp + (((luh + 4) ^ (r & 7)) * 16));
            }
#pragma unroll
            for (int np = 0; np < 4; np++) {
                const int r  = wn * 64 + np * 16 + ((lid >> 4) & 1) * 8 + (lid & 7);
                const int lu = ks * 2 + ((lid >> 3) & 1);
                ldsm_x4(bf[np], bBase + r * 128 + ((lu ^ (r & 7)) * 16));
            }
#pragma unroll
            for (int mt = 0; mt < 4; mt++)
#pragma unroll
                for (int nt = 0; nt < 8; nt++)
                    mma16816h(acc[mt][nt], ahf[mt],
                              bf[nt >> 1][(nt & 1) * 2], bf[nt >> 1][(nt & 1) * 2 + 1]);
            if (do_lo) {
#pragma unroll
                for (int mt = 0; mt < 4; mt++)
#pragma unroll
                    for (int nt = 0; nt < 8; nt++)
                        mma16816h(acc[mt][nt], alf[mt],
                                  bf[nt >> 1][(nt & 1) * 2],
                                  bf[nt >> 1][(nt & 1) * 2 + 1]);
            }
        }
    }

#pragma unroll
    for (int mt = 0; mt < 4; mt++) {
        const int r = row0 + wm * 64 + mt * 16 + (lid >> 2);
#pragma unroll
        for (int nt = 0; nt < 8; nt++) {
            const int cc = col0 + wn * 64 + nt * 8 + (lid & 3) * 2;
            *(float2*)&C[(size_t)r * Ntot + cc] =
                make_float2(acc[mt][nt][0], acc[mt][nt][1]);
            *(float2*)&C[(size_t)(r + 8) * Ntot + cc] =
                make_float2(acc[mt][nt][2], acc[mt][nt][3]);
        }
    }
}

// Item-based fused QKV. 768 items (heavy K items first):
//  [0,128):   K   kh=t&1, cb=(t>>1)&3,  rb=t>>3, 2-pass   (heaviest)
//  [128,640): Q   kh=t&1, cb=(t>>1)&15, rb=t>>5, 1-pass
//  [640,768): V   kh=t&1, cb=(t>>1)&3,  rb=t>>3, 1-pass
// Each item covers K chunks [kh*32, kh*32+32), writes fp32 partials.
__global__ void __launch_bounds__(256, 1)
gemm_qkv16(const __half* __restrict__ xh, const __half* __restrict__ xl,
           const __half* __restrict__ wq16, const __half* __restrict__ wk16,
           const __half* __restrict__ wv16,
           float* __restrict__ qA, float* __restrict__ qB,
           float* __restrict__ kA, float* __restrict__ kB,
           float* __restrict__ vA, float* __restrict__ vB)
{
    extern __shared__ char smraw[];
    const int idx = blockIdx.x;
    const __half* B; float* C; int Ntot, col0, row0, kh; bool do_lo;
    if (idx < 128) {
        const int t = idx;
        kh = t & 1;
        col0 = ((t >> 1) & 3) * 256;
        row0 = (t >> 3) * 128;
        B = wk16; C = kh ? kB : kA; Ntot = KVDIM; do_lo = true;
    } else if (idx < 640) {
        const int t = idx - 128;
        kh = t & 1;
        col0 = ((t >> 1) & 15) * 256;
        row0 = (t >> 5) * 128;
        B = wq16; C = kh ? qB : qA; Ntot = DIM; do_lo = false;
    } else {
        const int t = idx - 640;
        kh = t & 1;
        col0 = ((t >> 1) & 3) * 256;
        row0 = (t >> 3) * 128;
        B = wv16; C = kh ? vB : vA; Ntot = KVDIM; do_lo = false;
    }
    gemm_f16_2p_body(xh, xl, B, C, Ntot, row0, col0,
                     kh * 32, kh * 32 + 32, do_lo, smraw);
}

// ---------------------------------------------------------------------------
// fp16 1-pass GEMM (output projection): C = Yh @ Wo^T.
// CTA tile 128x256, K-chunk 64. Stage 48KB: A 16K | B 32K.
// ---------------------------------------------------------------------------
#define F1_STAGE 49152
#define F1_SMEM  (3 * F1_STAGE + 1024)
#define F1_NC    (DIM / 64)

__device__ __forceinline__ void f1_stage_load(
    uint32_t st, const __half* __restrict__ A, const __half* __restrict__ B,
    int row0, int col0, int k0, int tid)
{
    const int r  = tid >> 1;
    const int h  = tid & 1;
    const int sw = r & 7;
    {
        const __half* src = A + (size_t)(row0 + r) * DIM + k0 + h * 32;
        const uint32_t rowp = st + r * 128;
#pragma unroll
        for (int u = 0; u < 4; u++)
            CP_ASYNC16(rowp + (((h * 4 + u) ^ sw) * 16), src + u * 8);
    }
#pragma unroll
    for (int p = 0; p < 2; p++) {
        const int rb = r + p * 128;
        const int swb = rb & 7;
        const __half* src = B + (size_t)(col0 + rb) * DIM + k0 + h * 32;
        const uint32_t rowp = st + 16384 + rb * 128;
#pragma unroll
        for (int u = 0; u < 4; u++)
            CP_ASYNC16(rowp + (((h * 4 + u) ^ swb) * 16), src + u * 8);
    }
}

__global__ void __launch_bounds__(256, 1)
gemm_f16_1p(const __half* __restrict__ Yh, const __half* __restrict__ Wo,
            float* __restrict__ C, int Ntot)
{
    extern __shared__ char smraw[];
    const uint32_t sbase = (smem_u32(smraw) + 1023u) & ~1023u;
    const int tid = threadIdx.x;
    const int lid = tid & 31;
    const int wid = tid >> 5;
    const int wm  = wid & 1;
    const int wn  = wid >> 1;
    const int row0 = blockIdx.y * 128;
    const int col0 = blockIdx.x * 256;

    float acc[4][8][4];
#pragma unroll
    for (int i = 0; i < 4; i++)
#pragma unroll
        for (int j = 0; j < 8; j++)
#pragma unroll
            for (int q = 0; q < 4; q++) acc[i][j][q] = 0.f;

    f1_stage_load(sbase,            Yh, Wo, row0, col0, 0,  tid);
    CP_COMMIT();
    f1_stage_load(sbase + F1_STAGE, Yh, Wo, row0, col0, 64, tid);
    CP_COMMIT();

    int cur = 0, nxt = 2;
    for (int c = 0; c < F1_NC; c++) {
        CP_WAIT1();
        __syncthreads();
        if (c + 2 < F1_NC) {
            f1_stage_load(sbase + nxt * F1_STAGE,
                          Yh, Wo, row0, col0, (c + 2) * 64, tid);
            CP_COMMIT();
        }
        const uint32_t aBase = sbase + cur * F1_STAGE;
        const uint32_t bBase = aBase + 16384;
        cur = (cur == 2) ? 0 : cur + 1;
        nxt = (nxt == 2) ? 0 : nxt + 1;

#pragma unroll
        for (int ks = 0; ks < 4; ks++) {
            uint32_t af[4][4], bf[4][4];
#pragma unroll
            for (int mt = 0; mt < 4; mt++) {
                const int r = wm * 64 + mt * 16 + (lid & 15);
                const int lu = ks * 2 + (lid >> 4);
                ldsm_x4(af[mt], aBase + r * 128 + ((lu ^ (r & 7)) * 16));
            }
#pragma unroll
            for (int np = 0; np < 4; np++) {
                const int r  = wn * 64 + np * 16 + ((lid >> 4) & 1) * 8 + (lid & 7);
                const int lu = ks * 2 + ((lid >> 3) & 1);
                ldsm_x4(bf[np], bBase + r * 128 + ((lu ^ (r & 7)) * 16));
            }
#pragma unroll
            for (int mt = 0; mt < 4; mt++)
#pragma unroll
                for (int nt = 0; nt < 8; nt++)
                    mma16816h(acc[mt][nt], af[mt],
                              bf[nt >> 1][(nt & 1) * 2], bf[nt >> 1][(nt & 1) * 2 + 1]);
        }
    }

#pragma unroll
    for (int mt = 0; mt < 4; mt++) {
        const int r = row0 + wm * 64 + mt * 16 + (lid >> 2);
#pragma unroll
        for (int nt = 0; nt < 8; nt++) {
            const int cc = col0 + wn * 64 + nt * 8 + (lid & 3) * 2;
            *(float2*)&C[(size_t)r * Ntot + cc] =
                make_float2(acc[mt][nt][0], acc[mt][nt][1]);
            *(float2*)&C[(size_t)(r + 8) * Ntot + cc] =
                make_float2(acc[mt][nt][2], acc[mt][nt][3]);
        }
    }
}

// ---------------------------------------------------------------------------
// fp16 single-pass flash attention. Br=128, Bc=64, causal, GQA 4.
// Heaviest q-tiles dispatched first (qt reversed).
// ---------------------------------------------------------------------------
#define AT_Q 0
#define AT_ST(b) (32768 + (b) * 32768)
#define AT_K 0
#define AT_V 16384
#define AT_SMEM (32768 + 2 * 32768)

__device__ __forceinline__ void attn_load_kv(
    uint32_t stage, const __half* __restrict__ K16,
    const __half* __restrict__ Vt16, int j, int kvh, int tid)
{
    for (int idx = tid; idx < 1024; idx += 256) {
        const int r = idx >> 4, u = idx & 15;
        const int phys = ((u ^ (r & 7)) * 16);
        const size_t gk = ((size_t)(j * 64 + r) * NKV + kvh) * HD + u * 8;
        CP_ASYNC16(stage + AT_K + r * 256 + phys, K16 + gk);
    }
    for (int idx = tid; idx < 1024; idx += 256) {
        const int r = idx >> 3, u = idx & 7;
        const int phys = ((u ^ (r & 7)) * 16);
        const size_t gv = ((size_t)(kvh * 128 + r)) * SEQ + j * 64 + u * 8;
        CP_ASYNC16(stage + AT_V + r * 128 + phys, Vt16 + gv);
    }
}

__global__ void __launch_bounds__(256)
attn_f16_kernel(const __half* __restrict__ Q16,
                const __half* __restrict__ K16,
                const __half* __restrict__ Vt16,
                __half* __restrict__ Yh)
{
    extern __shared__ char smraw[];
    const uint32_t sb = smem_u32(smraw);

    const int qt  = (int)gridDim.x - 1 - (int)blockIdx.x;  // heavy first
    const int h   = blockIdx.y;
    const int kvh = h >> 2;
    const int tid = threadIdx.x;
    const int lid = tid & 31;
    const int wid = tid >> 5;
    const int qrow0 = qt * 128;

    for (int idx = tid; idx < 2048; idx += 256) {
        const int r = idx >> 4, u = idx & 15;
        const int phys = ((u ^ (r & 7)) * 16);
        const size_t g = ((size_t)(qrow0 + r) * NH + h) * HD + u * 8;
        CP_ASYNC16(sb + AT_Q + r * 256 + phys, Q16 + g);
    }
    attn_load_kv(sb + AT_ST(0), K16, Vt16, 0, kvh, tid);
    CP_COMMIT();

    float o[16][4];
#pragma unroll
    for (int dt = 0; dt < 16; dt++)
#pragma unroll
        for (int q = 0; q < 4; q++) o[dt][q] = 0.f;
    float mA = -1e30f, mB = -1e30f, lA = 0.f, lB = 0.f;

    const int g  = lid >> 2;
    const int cA = (lid & 3) * 2;
    const int jEnd = 2 * qt + 1;

    for (int j = 0; j <= jEnd; j++) {
        CP_WAIT0();
        __syncthreads();
        if (j < jEnd) {
            attn_load_kv(sb + AT_ST((j + 1) & 1), K16, Vt16, j + 1, kvh, tid);
            CP_COMMIT();
        }
        const uint32_t kb = sb + AT_ST(j & 1);

        float s[8][4];
#pragma unroll
        for (int nt = 0; nt < 8; nt++)
#pragma unroll
            for (int q = 0; q < 4; q++) s[nt][q] = 0.f;

#pragma unroll
        for (int kc = 0; kc < 8; kc++) {
            uint32_t qf[4];
            const int rA = wid * 16 + (lid & 15);
            const int uA = kc * 2 + (lid >> 4);
            ldsm_x4(qf, sb + AT_Q + rA * 256 + ((uA ^ (rA & 7)) * 16));
#pragma unroll
            for (int np = 0; np < 4; np++) {
                uint32_t kf[4];
                const int rB = np * 16 + ((lid >> 4) & 1) * 8 + (lid & 7);
                const int uB = kc * 2 + ((lid >> 3) & 1);
                ldsm_x4(kf, kb + AT_K + rB * 256 + ((uB ^ (rB & 7)) * 16));
#pragma unroll
                for (int hf = 0; hf < 2; hf++)
                    mma16816h(s[np * 2 + hf], qf, kf[hf * 2], kf[hf * 2 + 1]);
            }
        }

        if (j >= 2 * qt) {
            const int rowA = qrow0 + wid * 16 + g;
            const int colBase = j * 64;
#pragma unroll
            for (int nt = 0; nt < 8; nt++) {
                const int col = colBase + nt * 8 + cA;
                if (col     > rowA)     s[nt][0] = -1e30f;
                if (col + 1 > rowA)     s[nt][1] = -1e30f;
                if (col     > rowA + 8) s[nt][2] = -1e30f;
                if (col + 1 > rowA + 8) s[nt][3] = -1e30f;
            }
        }

        float mxA = -1e30f, mxB = -1e30f;
#pragma unroll
        for (int nt = 0; nt < 8; nt++) {
            mxA = fmaxf(mxA, fmaxf(s[nt][0], s[nt][1]));
            mxB = fmaxf(mxB, fmaxf(s[nt][2], s[nt][3]));
        }
        mxA = fmaxf(mxA, __shfl_xor_sync(0xffffffffu, mxA, 1));
        mxA = fmaxf(mxA, __shfl_xor_sync(0xffffffffu, mxA, 2));
        mxB = fmaxf(mxB, __shfl_xor_sync(0xffffffffu, mxB, 1));
        mxB = fmaxf(mxB, __shfl_xor_sync(0xffffffffu, mxB, 2));
        const float mnA = fmaxf(mA, mxA), mnB = fmaxf(mB, mxB);
        const float alA = __expf(mA - mnA), alB = __expf(mB - mnB);

        uint32_t p[8][2];
        float rsA = 0.f, rsB = 0.f;
#pragma unroll
        for (int nt = 0; nt < 8; nt++) {
            float p0 = __expf(s[nt][0] - mnA);
            float p1 = __expf(s[nt][1] - mnA);
            float p2 = __expf(s[nt][2] - mnB);
            float p3 = __expf(s[nt][3] - mnB);
            rsA += p0 + p1;  rsB += p2 + p3;
            __half2 a0 = __floats2half2_rn(p0, p1);
            __half2 a1 = __floats2half2_rn(p2, p3);
            p[nt][0] = *reinterpret_cast<uint32_t*>(&a0);
            p[nt][1] = *reinterpret_cast<uint32_t*>(&a1);
        }
        rsA += __shfl_xor_sync(0xffffffffu, rsA, 1);
        rsA += __shfl_xor_sync(0xffffffffu, rsA, 2);
        rsB += __shfl_xor_sync(0xffffffffu, rsB, 1);
        rsB += __shfl_xor_sync(0xffffffffu, rsB, 2);
        lA = lA * alA + rsA;  mA = mnA;
        lB = lB * alB + rsB;  mB = mnB;

#pragma unroll
        for (int dt = 0; dt < 16; dt++) {
            o[dt][0] *= alA; o[dt][1] *= alA;
            o[dt][2] *= alB; o[dt][3] *= alB;
        }

#pragma unroll
        for (int kc = 0; kc < 4; kc++) {
            uint32_t a[4] = { p[2 * kc][0], p[2 * kc][1],
                              p[2 * kc + 1][0], p[2 * kc + 1][1] };
#pragma unroll
            for (int dp = 0; dp < 8; dp++) {
                uint32_t vf[4];
                const int rB = dp * 16 + ((lid >> 4) & 1) * 8 + (lid & 7);
                const int uB = kc * 2 + ((lid >> 3) & 1);
                ldsm_x4(vf, kb + AT_V + rB * 128 + ((uB ^ (rB & 7)) * 16));
#pragma unroll
                for (int hf = 0; hf < 2; hf++)
                    mma16816h(o[dp * 2 + hf], a, vf[hf * 2], vf[hf * 2 + 1]);
            }
        }
    }

    const float invA = 1.f / lA, invB = 1.f / lB;
    const int rowA = qrow0 + wid * 16 + g;
#pragma unroll
    for (int dt = 0; dt < 16; dt++) {
        const int d = h * HD + dt * 8 + cA;
        *(__half2*)&Yh[(size_t)rowA * DIM + d] =
            __floats2half2_rn(o[dt][0] * invA, o[dt][1] * invA);
        *(__half2*)&Yh[(size_t)(rowA + 8) * DIM + d] =
            __floats2half2_rn(o[dt][2] * invB, o[dt][3] * invB);
    }
}

// ---------------------------------------------------------------------------
// Launch
// ---------------------------------------------------------------------------
extern "C" void kernel_launch(void* const* d_in, const int* in_sizes, int n_in,
                              void* d_out, int out_size)
{
    const float* x  = (const float*)d_in[0];
    const float* fc = (const float*)d_in[1];
    const float* wq = (const float*)d_in[3];
    const float* wk = (const float*)d_in[4];
    const float* wv = (const float*)d_in[5];
    const float* wo = (const float*)d_in[6];
    float* out = (float*)d_out;

    float *qA, *qB, *kA, *kB, *vA, *vB;
    cudaGetSymbolAddress((void**)&qA, g_qA); cudaGetSymbolAddress((void**)&qB, g_qB);
    cudaGetSymbolAddress((void**)&kA, g_kA); cudaGetSymbolAddress((void**)&kB, g_kB);
    cudaGetSymbolAddress((void**)&vA, g_vA); cudaGetSymbolAddress((void**)&vB, g_vB);

    __half *xh16, *xl16, *wq16, *wk16, *wv16, *wo16, *yh16, *q16, *k16, *vt16;
    cudaGetSymbolAddress((void**)&xh16, g_xh16);
    cudaGetSymbolAddress((void**)&xl16, g_xl16);
    cudaGetSymbolAddress((void**)&wq16, g_wq16);
    cudaGetSymbolAddress((void**)&wk16, g_wk16);
    cudaGetSymbolAddress((void**)&wv16, g_wv16);
    cudaGetSymbolAddress((void**)&wo16, g_wo16);
    cudaGetSymbolAddress((void**)&yh16, g_yh16);
    cudaGetSymbolAddress((void**)&q16,  g_q16);
    cudaGetSymbolAddress((void**)&k16,  g_k16);
    cudaGetSymbolAddress((void**)&vt16, g_vt16);

    cudaFuncSetAttribute(gemm_qkv16,
                         cudaFuncAttributeMaxDynamicSharedMemorySize, F2_SMEM);
    cudaFuncSetAttribute(gemm_f16_1p,
                         cudaFuncAttributeMaxDynamicSharedMemorySize, F1_SMEM);
    cudaFuncSetAttribute(attn_f16_kernel,
                         cudaFuncAttributeMaxDynamicSharedMemorySize, AT_SMEM);

    const int T = 256;
    split16_kernel<<<(SEQ * DIM / 8 + T - 1) / T, T>>>(x, xh16, xl16, SEQ * DIM / 8);
    trunc16_kernel<<<(DIM * DIM / 8 + T - 1) / T, T>>>(wq, wq16, DIM * DIM / 8);
    trunc16_kernel<<<(KVDIM * DIM / 8 + T - 1) / T, T>>>(wk, wk16, KVDIM * DIM / 8);
    trunc16_kernel<<<(KVDIM * DIM / 8 + T - 1) / T, T>>>(wv, wv16, KVDIM * DIM / 8);
    trunc16_kernel<<<(DIM * DIM / 8 + T - 1) / T, T>>>(wo, wo16, DIM * DIM / 8);

    // Fused QKV projection: 768 K-split items (K 2-pass first, Q/V 1-pass)
    gemm_qkv16<<<768, 256, F2_SMEM>>>(
        xh16, xl16, wq16, wk16, wv16, qA, qB, kA, kB, vA, vB);

    // RoPE on partial sums -> fp16; V partial-sum transpose -> fp16
    const float scale = 0.08838834764831845f;
    rope_sum_f16_kernel<<<(SEQ * NH  * 64 + T - 1) / T, T>>>(
        qA, qB, fc, q16, NH,  scale, SEQ * NH  * 64);
    rope_sum_f16_kernel<<<(SEQ * NKV * 64 + T - 1) / T, T>>>(
        kA, kB, fc, k16, NKV, 1.0f,  SEQ * NKV * 64);
    vt_sum_f16_kernel<<<(KVDIM * SEQ + T - 1) / T, T>>>(vA, vB, vt16);

    // Attention (fp16 single-pass, heavy tiles first)
    attn_f16_kernel<<<dim3(SEQ / 128, NH), 256, AT_SMEM>>>(
        q16, k16, vt16, yh16);

    // Output projection (fp16 1-pass)
    gemm_f16_1p<<<dim3(DIM / 256, SEQ / 128), 256, F1_SMEM>>>(
        yh16, wo16, out, DIM);
}

// round 17
// speedup vs baseline: 1.1925x; 1.1925x over previous
#include <cuda_runtime.h>
#include <cuda_bf16.h>
#include <cuda_fp16.h>
#include <math.h>
#include <stdint.h>

#define SEQ    2048
#define DIM    4096
#define NH     32
#define NKV    8
#define HD     128
#define KVDIM  (NKV*HD)

// ---------------------------------------------------------------------------
// Scratch (device globals)
// ---------------------------------------------------------------------------
static __device__ float g_qA[SEQ * DIM],   g_qB[SEQ * DIM];
static __device__ float g_kA[SEQ * KVDIM], g_kB[SEQ * KVDIM];
static __device__ float g_vA[SEQ * KVDIM], g_vB[SEQ * KVDIM];

static __device__ __half g_x16[SEQ * DIM];
static __device__ __half g_wq16[DIM * DIM];
static __device__ __half g_wk16[KVDIM * DIM];
static __device__ __half g_wv16[KVDIM * DIM];
static __device__ __half g_wo16[DIM * DIM];
static __device__ __half g_yh16[SEQ * DIM];

static __device__ __half g_q16[SEQ * DIM];
static __device__ __half g_k16[SEQ * KVDIM];
static __device__ __half g_vt16[KVDIM * SEQ];   // [kvh*128+d][s]

// ---------------------------------------------------------------------------
// Helpers
// ---------------------------------------------------------------------------
__device__ __forceinline__ uint32_t smem_u32(const void* p) {
    uint32_t a;
    asm("{ .reg .u64 t; cvta.to.shared.u64 t, %1; cvt.u32.u64 %0, t; }"
        : "=r"(a) : "l"(p));
    return a;
}

__device__ __forceinline__ void ldsm_x4(uint32_t* d, uint32_t addr) {
    asm volatile("ldmatrix.sync.aligned.m8n8.x4.shared.b16 {%0,%1,%2,%3}, [%4];"
                 : "=r"(d[0]), "=r"(d[1]), "=r"(d[2]), "=r"(d[3]) : "r"(addr));
}

__device__ __forceinline__ void mma16816h(float* c, const uint32_t* a,
                                          uint32_t b0, uint32_t b1) {
    asm volatile(
        "mma.sync.aligned.m16n8k16.row.col.f32.f16.f16.f32 "
        "{%0,%1,%2,%3}, {%4,%5,%6,%7}, {%8,%9}, {%0,%1,%2,%3};"
        : "+f"(c[0]), "+f"(c[1]), "+f"(c[2]), "+f"(c[3])
        : "r"(a[0]), "r"(a[1]), "r"(a[2]), "r"(a[3]), "r"(b0), "r"(b1));
}

#define CP_ASYNC16(dst, src) \
    asm volatile("cp.async.cg.shared.global [%0], [%1], 16;" :: "r"(dst), "l"(src))
#define CP_COMMIT() asm volatile("cp.async.commit_group;" ::: "memory")
#define CP_WAIT1()  asm volatile("cp.async.wait_group 1;"  ::: "memory")
#define CP_WAIT0()  asm volatile("cp.async.wait_group 0;"  ::: "memory")

// ---------------------------------------------------------------------------
// Fused fp32 -> fp16 truncation over x, wq, wk, wv, wo (one launch).
// Ranges in n8 units: x 1<<20 | wq 2<<20 | wk 1<<19 | wv 1<<19 | wo 2<<20.
// ---------------------------------------------------------------------------
#define N8_X   (SEQ * DIM / 8)            // 1048576
#define N8_WQ  (DIM * DIM / 8)            // 2097152
#define N8_WKV (KVDIM * DIM / 8)          // 524288
#define N8_TOT (N8_X + N8_WQ + 2 * N8_WKV + N8_WQ)

__global__ void trunc_all_kernel(
    const float* __restrict__ x,  __half* __restrict__ xo,
    const float* __restrict__ wq, __half* __restrict__ wqo,
    const float* __restrict__ wk, __half* __restrict__ wko,
    const float* __restrict__ wv, __half* __restrict__ wvo,
    const float* __restrict__ wo, __half* __restrict__ woo)
{
    int i = blockIdx.x * blockDim.x + threadIdx.x;
    if (i >= N8_TOT) return;
    const float* in; __half* out; int base;
    if (i < N8_X)                        { in = x;  out = xo;  base = 0; }
    else if (i < N8_X + N8_WQ)           { in = wq; out = wqo; base = N8_X; }
    else if (i < N8_X + N8_WQ + N8_WKV)  { in = wk; out = wko; base = N8_X + N8_WQ; }
    else if (i < N8_X + N8_WQ + 2 * N8_WKV)
                                         { in = wv; out = wvo; base = N8_X + N8_WQ + N8_WKV; }
    else                                 { in = wo; out = woo; base = N8_X + N8_WQ + 2 * N8_WKV; }
    const int j = i - base;
#pragma unroll
    for (int half = 0; half < 2; half++) {
        float4 v = ((const float4*)in)[2 * j + half];
        __half2* op = (__half2*)out;
        op[4 * j + 2 * half]     = __floats2half2_rn(v.x, v.y);
        op[4 * j + 2 * half + 1] = __floats2half2_rn(v.z, v.w);
    }
}

// RoPE + scale on sum of two fp32 partials -> fp16
__global__ void rope_sum_f16_kernel(const float* __restrict__ xA,
                                    const float* __restrict__ xB,
                                    const float* __restrict__ fc,
                                    __half* __restrict__ o,
                                    int nheads, float scale, int total)
{
    int idx = blockIdx.x * blockDim.x + threadIdx.x;
    if (idx >= total) return;
    const int i = idx & 63;
    const int h = (idx >> 6) % nheads;
    const int s = idx / (64 * nheads);
    const float c  = fc[(s * 64 + i) * 2 + 0];
    const float sn = fc[(s * 64 + i) * 2 + 1];
    const size_t off = ((size_t)s * nheads + h) * HD + 2 * i;
    float2 va = *(const float2*)(xA + off);
    float2 vb = *(const float2*)(xB + off);
    const float vx = va.x + vb.x, vy = va.y + vb.y;
    float a = (vx * c - vy * sn) * scale;
    float b = (vy * c + vx * sn) * scale;
    *(__half2*)(o + off) = __floats2half2_rn(a, b);
}

// V transpose of partial sum -> fp16: [s][dl] -> [dl][s]
__global__ void vt_sum_f16_kernel(const float* __restrict__ vA,
                                  const float* __restrict__ vB,
                                  __half* __restrict__ vt)
{
    int idx = blockIdx.x * blockDim.x + threadIdx.x;
    const int s = idx & (SEQ - 1);
    const int dl = idx >> 11;
    if (dl >= KVDIM) return;
    const size_t off = (size_t)s * KVDIM + dl;
    vt[idx] = __float2half_rn(vA[off] + vB[off]);
}

// ---------------------------------------------------------------------------
// fp16 1-pass GEMM body over chunk range [c0, c1): C = A @ B^T (fp32 out).
// CTA tile 128x256, 8 warps (2x4), K-chunk 64, 3-stage cp.async.
// Stage 48KB: A 16K (128 rows x 128B) | B 32K (256 rows x 128B).
// ---------------------------------------------------------------------------
#define F1_STAGE 49152
#define F1_SMEM  (3 * F1_STAGE + 1024)

__device__ __forceinline__ void f1_stage_load(
    uint32_t st, const __half* __restrict__ A, const __half* __restrict__ B,
    int row0, int col0, int k0, int tid)
{
    const int r  = tid >> 1;
    const int h  = tid & 1;
    const int sw = r & 7;
    {
        const __half* src = A + (size_t)(row0 + r) * DIM + k0 + h * 32;
        const uint32_t rowp = st + r * 128;
#pragma unroll
        for (int u = 0; u < 4; u++)
            CP_ASYNC16(rowp + (((h * 4 + u) ^ sw) * 16), src + u * 8);
    }
#pragma unroll
    for (int p = 0; p < 2; p++) {
        const int rb = r + p * 128;
        const int swb = rb & 7;
        const __half* src = B + (size_t)(col0 + rb) * DIM + k0 + h * 32;
        const uint32_t rowp = st + 16384 + rb * 128;
#pragma unroll
        for (int u = 0; u < 4; u++)
            CP_ASYNC16(rowp + (((h * 4 + u) ^ swb) * 16), src + u * 8);
    }
}

__device__ __forceinline__ void gemm_f16_1p_body(
    const __half* __restrict__ A, const __half* __restrict__ B,
    float* __restrict__ C, int Ntot, int row0, int col0,
    int c0, int c1, char* smraw)
{
    const uint32_t sbase = (smem_u32(smraw) + 1023u) & ~1023u;
    const int tid = threadIdx.x;
    const int lid = tid & 31;
    const int wid = tid >> 5;
    const int wm  = wid & 1;
    const int wn  = wid >> 1;

    float acc[4][8][4];
#pragma unroll
    for (int i = 0; i < 4; i++)
#pragma unroll
        for (int j = 0; j < 8; j++)
#pragma unroll
            for (int q = 0; q < 4; q++) acc[i][j][q] = 0.f;

    f1_stage_load(sbase,            A, B, row0, col0, c0 * 64,       tid);
    CP_COMMIT();
    f1_stage_load(sbase + F1_STAGE, A, B, row0, col0, (c0 + 1) * 64, tid);
    CP_COMMIT();

    int cur = 0, nxt = 2;
    for (int c = c0; c < c1; c++) {
        CP_WAIT1();
        __syncthreads();
        if (c + 2 < c1) {
            f1_stage_load(sbase + nxt * F1_STAGE,
                          A, B, row0, col0, (c + 2) * 64, tid);
            CP_COMMIT();
        }
        const uint32_t aBase = sbase + cur * F1_STAGE;
        const uint32_t bBase = aBase + 16384;
        cur = (cur == 2) ? 0 : cur + 1;
        nxt = (nxt == 2) ? 0 : nxt + 1;

#pragma unroll
        for (int ks = 0; ks < 4; ks++) {
            uint32_t af[4][4], bf[4][4];
#pragma unroll
            for (int mt = 0; mt < 4; mt++) {
                const int r = wm * 64 + mt * 16 + (lid & 15);
                const int lu = ks * 2 + (lid >> 4);
                ldsm_x4(af[mt], aBase + r * 128 + ((lu ^ (r & 7)) * 16));
            }
#pragma unroll
            for (int np = 0; np < 4; np++) {
                const int r  = wn * 64 + np * 16 + ((lid >> 4) & 1) * 8 + (lid & 7);
                const int lu = ks * 2 + ((lid >> 3) & 1);
                ldsm_x4(bf[np], bBase + r * 128 + ((lu ^ (r & 7)) * 16));
            }
#pragma unroll
            for (int mt = 0; mt < 4; mt++)
#pragma unroll
                for (int nt = 0; nt < 8; nt++)
                    mma16816h(acc[mt][nt], af[mt],
                              bf[nt >> 1][(nt & 1) * 2], bf[nt >> 1][(nt & 1) * 2 + 1]);
        }
    }

#pragma unroll
    for (int mt = 0; mt < 4; mt++) {
        const int r = row0 + wm * 64 + mt * 16 + (lid >> 2);
#pragma unroll
        for (int nt = 0; nt < 8; nt++) {
            const int cc = col0 + wn * 64 + nt * 8 + (lid & 3) * 2;
            *(float2*)&C[(size_t)r * Ntot + cc] =
                make_float2(acc[mt][nt][0], acc[mt][nt][1]);
            *(float2*)&C[(size_t)(r + 8) * Ntot + cc] =
                make_float2(acc[mt][nt][2], acc[mt][nt][3]);
        }
    }
}

// Item-based fused QKV, all 1-pass, uniform items. 768 items:
//  [0,512):   Q   kh=t&1, cb=(t>>1)&15, rb=t>>5
//  [512,640): K   kh=t&1, cb=(t>>1)&3,  rb=t>>3
//  [640,768): V   kh=t&1, cb=(t>>1)&3,  rb=t>>3
// Each item covers K chunks [kh*32, kh*32+32), writes fp32 partials.
__global__ void __launch_bounds__(256, 1)
gemm_qkv16(const __half* __restrict__ x16,
           const __half* __restrict__ wq16, const __half* __restrict__ wk16,
           const __half* __restrict__ wv16,
           float* __restrict__ qA, float* __restrict__ qB,
           float* __restrict__ kA, float* __restrict__ kB,
           float* __restrict__ vA, float* __restrict__ vB)
{
    extern __shared__ char smraw[];
    const int idx = blockIdx.x;
    const __half* B; float* C; int Ntot, col0, row0, kh;
    if (idx < 512) {
        const int t = idx;
        kh = t & 1;
        col0 = ((t >> 1) & 15) * 256;
        row0 = (t >> 5) * 128;
        B = wq16; C = kh ? qB : qA; Ntot = DIM;
    } else if (idx < 640) {
        const int t = idx - 512;
        kh = t & 1;
        col0 = ((t >> 1) & 3) * 256;
        row0 = (t >> 3) * 128;
        B = wk16; C = kh ? kB : kA; Ntot = KVDIM;
    } else {
        const int t = idx - 640;
        kh = t & 1;
        col0 = ((t >> 1) & 3) * 256;
        row0 = (t >> 3) * 128;
        B = wv16; C = kh ? vB : vA; Ntot = KVDIM;
    }
    gemm_f16_1p_body(x16, B, C, Ntot, row0, col0, kh * 32, kh * 32 + 32, smraw);
}

// Output projection (full K range)
__global__ void __launch_bounds__(256, 1)
gemm_out1p(const __half* __restrict__ Yh, const __half* __restrict__ Wo,
           float* __restrict__ C)
{
    extern __shared__ char smraw[];
    gemm_f16_1p_body(Yh, Wo, C, DIM, blockIdx.y * 128, blockIdx.x * 256,
                     0, DIM / 64, smraw);
}

// ---------------------------------------------------------------------------
// fp16 single-pass flash attention. Br=128, Bc=64, causal, GQA 4.
// Heaviest q-tiles dispatched first (qt reversed).
// ---------------------------------------------------------------------------
#define AT_Q 0
#define AT_ST(b) (32768 + (b) * 32768)
#define AT_K 0
#define AT_V 16384
#define AT_SMEM (32768 + 2 * 32768)

__device__ __forceinline__ void attn_load_kv(
    uint32_t stage, const __half* __restrict__ K16,
    const __half* __restrict__ Vt16, int j, int kvh, int tid)
{
    for (int idx = tid; idx < 1024; idx += 256) {
        const int r = idx >> 4, u = idx & 15;
        const int phys = ((u ^ (r & 7)) * 16);
        const size_t gk = ((size_t)(j * 64 + r) * NKV + kvh) * HD + u * 8;
        CP_ASYNC16(stage + AT_K + r * 256 + phys, K16 + gk);
    }
    for (int idx = tid; idx < 1024; idx += 256) {
        const int r = idx >> 3, u = idx & 7;
        const int phys = ((u ^ (r & 7)) * 16);
        const size_t gv = ((size_t)(kvh * 128 + r)) * SEQ + j * 64 + u * 8;
        CP_ASYNC16(stage + AT_V + r * 128 + phys, Vt16 + gv);
    }
}

__global__ void __launch_bounds__(256)
attn_f16_kernel(const __half* __restrict__ Q16,
                const __half* __restrict__ K16,
                const __half* __restrict__ Vt16,
                __half* __restrict__ Yh)
{
    extern __shared__ char smraw[];
    const uint32_t sb = smem_u32(smraw);

    const int qt  = (int)gridDim.x - 1 - (int)blockIdx.x;  // heavy first
    const int h   = blockIdx.y;
    const int kvh = h >> 2;
    const int tid = threadIdx.x;
    const int lid = tid & 31;
    const int wid = tid >> 5;
    const int qrow0 = qt * 128;

    for (int idx = tid; idx < 2048; idx += 256) {
        const int r = idx >> 4, u = idx & 15;
        const int phys = ((u ^ (r & 7)) * 16);
        const size_t g = ((size_t)(qrow0 + r) * NH + h) * HD + u * 8;
        CP_ASYNC16(sb + AT_Q + r * 256 + phys, Q16 + g);
    }
    attn_load_kv(sb + AT_ST(0), K16, Vt16, 0, kvh, tid);
    CP_COMMIT();

    float o[16][4];
#pragma unroll
    for (int dt = 0; dt < 16; dt++)
#pragma unroll
        for (int q = 0; q < 4; q++) o[dt][q] = 0.f;
    float mA = -1e30f, mB = -1e30f, lA = 0.f, lB = 0.f;

    const int g  = lid >> 2;
    const int cA = (lid & 3) * 2;
    const int jEnd = 2 * qt + 1;

    for (int j = 0; j <= jEnd; j++) {
        CP_WAIT0();
        __syncthreads();
        if (j < jEnd) {
            attn_load_kv(sb + AT_ST((j + 1) & 1), K16, Vt16, j + 1, kvh, tid);
            CP_COMMIT();
        }
        const uint32_t kb = sb + AT_ST(j & 1);

        float s[8][4];
#pragma unroll
        for (int nt = 0; nt < 8; nt++)
#pragma unroll
            for (int q = 0; q < 4; q++) s[nt][q] = 0.f;

#pragma unroll
        for (int kc = 0; kc < 8; kc++) {
            uint32_t qf[4];
            const int rA = wid * 16 + (lid & 15);
            const int uA = kc * 2 + (lid >> 4);
            ldsm_x4(qf, sb + AT_Q + rA * 256 + ((uA ^ (rA & 7)) * 16));
#pragma unroll
            for (int np = 0; np < 4; np++) {
                uint32_t kf[4];
                const int rB = np * 16 + ((lid >> 4) & 1) * 8 + (lid & 7);
                const int uB = kc * 2 + ((lid >> 3) & 1);
                ldsm_x4(kf, kb + AT_K + rB * 256 + ((uB ^ (rB & 7)) * 16));
#pragma unroll
                for (int hf = 0; hf < 2; hf++)
                    mma16816h(s[np * 2 + hf], qf, kf[hf * 2], kf[hf * 2 + 1]);
            }
        }

        if (j >= 2 * qt) {
            const int rowA = qrow0 + wid * 16 + g;
            const int colBase = j * 64;
#pragma unroll
            for (int nt = 0; nt < 8; nt++) {
                const int col = colBase + nt * 8 + cA;
                if (col     > rowA)     s[nt][0] = -1e30f;
                if (col + 1 > rowA)     s[nt][1] = -1e30f;
                if (col     > rowA + 8) s[nt][2] = -1e30f;
                if (col + 1 > rowA + 8) s[nt][3] = -1e30f;
            }
        }

        float mxA = -1e30f, mxB = -1e30f;
#pragma unroll
        for (int nt = 0; nt < 8; nt++) {
            mxA = fmaxf(mxA, fmaxf(s[nt][0], s[nt][1]));
            mxB = fmaxf(mxB, fmaxf(s[nt][2], s[nt][3]));
        }
        mxA = fmaxf(mxA, __shfl_xor_sync(0xffffffffu, mxA, 1));
        mxA = fmaxf(mxA, __shfl_xor_sync(0xffffffffu, mxA, 2));
        mxB = fmaxf(mxB, __shfl_xor_sync(0xffffffffu, mxB, 1));
        mxB = fmaxf(mxB, __shfl_xor_sync(0xffffffffu, mxB, 2));
        const float mnA = fmaxf(mA, mxA), mnB = fmaxf(mB, mxB);
        const float alA = __expf(mA - mnA), alB = __expf(mB - mnB);

        uint32_t p[8][2];
        float rsA = 0.f, rsB = 0.f;
#pragma unroll
        for (int nt = 0; nt < 8; nt++) {
            float p0 = __expf(s[nt][0] - mnA);
            float p1 = __expf(s[nt][1] - mnA);
            float p2 = __expf(s[nt][2] - mnB);
            float p3 = __expf(s[nt][3] - mnB);
            rsA += p0 + p1;  rsB += p2 + p3;
            __half2 a0 = __floats2half2_rn(p0, p1);
            __half2 a1 = __floats2half2_rn(p2, p3);
            p[nt][0] = *reinterpret_cast<uint32_t*>(&a0);
            p[nt][1] = *reinterpret_cast<uint32_t*>(&a1);
        }
        rsA += __shfl_xor_sync(0xffffffffu, rsA, 1);
        rsA += __shfl_xor_sync(0xffffffffu, rsA, 2);
        rsB += __shfl_xor_sync(0xffffffffu, rsB, 1);
        rsB += __shfl_xor_sync(0xffffffffu, rsB, 2);
        lA = lA * alA + rsA;  mA = mnA;
        lB = lB * alB + rsB;  mB = mnB;

#pragma unroll
        for (int dt = 0; dt < 16; dt++) {
            o[dt][0] *= alA; o[dt][1] *= alA;
            o[dt][2] *= alB; o[dt][3] *= alB;
        }

#pragma unroll
        for (int kc = 0; kc < 4; kc++) {
            uint32_t a[4] = { p[2 * kc][0], p[2 * kc][1],
                              p[2 * kc + 1][0], p[2 * kc + 1][1] };
#pragma unroll
            for (int dp = 0; dp < 8; dp++) {
                uint32_t vf[4];
                const int rB = dp * 16 + ((lid >> 4) & 1) * 8 + (lid & 7);
                const int uB = kc * 2 + ((lid >> 3) & 1);
                ldsm_x4(vf, kb + AT_V + rB * 128 + ((uB ^ (rB & 7)) * 16));
#pragma unroll
                for (int hf = 0; hf < 2; hf++)
                    mma16816h(o[dp * 2 + hf], a, vf[hf * 2], vf[hf * 2 + 1]);
            }
        }
    }

    const float invA = 1.f / lA, invB = 1.f / lB;
    const int rowA = qrow0 + wid * 16 + g;
#pragma unroll
    for (int dt = 0; dt < 16; dt++) {
        const int d = h * HD + dt * 8 + cA;
        *(__half2*)&Yh[(size_t)rowA * DIM + d] =
            __floats2half2_rn(o[dt][0] * invA, o[dt][1] * invA);
        *(__half2*)&Yh[(size_t)(rowA + 8) * DIM + d] =
            __floats2half2_rn(o[dt][2] * invB, o[dt][3] * invB);
    }
}

// ---------------------------------------------------------------------------
// Launch
// ---------------------------------------------------------------------------
extern "C" void kernel_launch(void* const* d_in, const int* in_sizes, int n_in,
                              void* d_out, int out_size)
{
    const float* x  = (const float*)d_in[0];
    const float* fc = (const float*)d_in[1];
    const float* wq = (const float*)d_in[3];
    const float* wk = (const float*)d_in[4];
    const float* wv = (const float*)d_in[5];
    const float* wo = (const float*)d_in[6];
    float* out = (float*)d_out;

    float *qA, *qB, *kA, *kB, *vA, *vB;
    cudaGetSymbolAddress((void**)&qA, g_qA); cudaGetSymbolAddress((void**)&qB, g_qB);
    cudaGetSymbolAddress((void**)&kA, g_kA); cudaGetSymbolAddress((void**)&kB, g_kB);
    cudaGetSymbolAddress((void**)&vA, g_vA); cudaGetSymbolAddress((void**)&vB, g_vB);

    __half *x16, *wq16, *wk16, *wv16, *wo16, *yh16, *q16, *k16, *vt16;
    cudaGetSymbolAddress((void**)&x16,  g_x16);
    cudaGetSymbolAddress((void**)&wq16, g_wq16);
    cudaGetSymbolAddress((void**)&wk16, g_wk16);
    cudaGetSymbolAddress((void**)&wv16, g_wv16);
    cudaGetSymbolAddress((void**)&wo16, g_wo16);
    cudaGetSymbolAddress((void**)&yh16, g_yh16);
    cudaGetSymbolAddress((void**)&q16,  g_q16);
    cudaGetSymbolAddress((void**)&k16,  g_k16);
    cudaGetSymbolAddress((void**)&vt16, g_vt16);

    cudaFuncSetAttribute(gemm_qkv16,
                         cudaFuncAttributeMaxDynamicSharedMemorySize, F1_SMEM);
    cudaFuncSetAttribute(gemm_out1p,
                         cudaFuncAttributeMaxDynamicSharedMemorySize, F1_SMEM);
    cudaFuncSetAttribute(attn_f16_kernel,
                         cudaFuncAttributeMaxDynamicSharedMemorySize, AT_SMEM);

    const int T = 256;
    // All fp32 -> fp16 conversions in one launch
    trunc_all_kernel<<<(N8_TOT + T - 1) / T, T>>>(
        x, x16, wq, wq16, wk, wk16, wv, wv16, wo, wo16);

    // Fused QKV projection: 768 uniform K-split 1-pass items
    gemm_qkv16<<<768, 256, F1_SMEM>>>(
        x16, wq16, wk16, wv16, qA, qB, kA, kB, vA, vB);

    // RoPE on partial sums -> fp16; V partial-sum transpose -> fp16
    const float scale = 0.08838834764831845f;
    rope_sum_f16_kernel<<<(SEQ * NH  * 64 + T - 1) / T, T>>>(
        qA, qB, fc, q16, NH,  scale, SEQ * NH  * 64);
    rope_sum_f16_kernel<<<(SEQ * NKV * 64 + T - 1) / T, T>>>(
        kA, kB, fc, k16, NKV, 1.0f,  SEQ * NKV * 64);
    vt_sum_f16_kernel<<<(KVDIM * SEQ + T - 1) / T, T>>>(vA, vB, vt16);

    // Attention (fp16 single-pass, heavy tiles first)
    attn_f16_kernel<<<dim3(SEQ / 128, NH), 256, AT_SMEM>>>(
        q16, k16, vt16, yh16);

    // Output projection (fp16 1-pass)
    gemm_out1p<<<dim3(DIM / 256, SEQ / 128), 256, F1_SMEM>>>(yh16, wo16, out);
}